// round 7
// baseline (speedup 1.0000x reference)
#include <cuda_runtime.h>
#include <cstdint>

#define BB 512
#define NN 2048
#define QDIM 64
#define HH 8
#define KDIM 8
#define VDIM 8
#define ODIM 64

// device scratch (no allocations allowed)
__device__ float g_qavg[BB * QDIM];          // [B][64]
__device__ float g_wavg[BB * HH * VDIM];     // [B][64]
__device__ float g_w1tf[QDIM * 64];          // gating_w pre-converted to tf32
__device__ float g_w2tf[QDIM * 64];          // output_w pre-converted to tf32

// ---------------------------------------------------------------------------
// helpers
// ---------------------------------------------------------------------------
__device__ __forceinline__ uint32_t f2tf32(float f) {
    uint32_t u;
    asm("cvt.rna.tf32.f32 %0, %1;" : "=r"(u) : "f"(f));
    return u;
}

__device__ __forceinline__ void mma_tf32(float c[4], const uint32_t a[4],
                                         const uint32_t b[2]) {
    asm volatile(
        "mma.sync.aligned.m16n8k8.row.col.f32.tf32.tf32.f32 "
        "{%0,%1,%2,%3}, {%4,%5,%6,%7}, {%8,%9}, {%0,%1,%2,%3};"
        : "+f"(c[0]), "+f"(c[1]), "+f"(c[2]), "+f"(c[3])
        : "r"(a[0]), "r"(a[1]), "r"(a[2]), "r"(a[3]), "r"(b[0]), "r"(b[1]));
}

typedef unsigned long long ull;
__device__ __forceinline__ ull pack2(float x, float y) {
    ull r;
    asm("mov.b64 %0, {%1, %2};" : "=l"(r) : "f"(x), "f"(y));
    return r;
}
__device__ __forceinline__ ull fma2(ull a, ull b, ull c) {
    ull d;
    asm("fma.rn.f32x2 %0, %1, %2, %3;" : "=l"(d) : "l"(a), "l"(b), "l"(c));
    return d;
}
__device__ __forceinline__ void unpack2(ull p, float& x, float& y) {
    asm("mov.b64 {%0, %1}, %2;" : "=f"(x), "=f"(y) : "l"(p));
}

// ---------------------------------------------------------------------------
// Kernel 0: one-time tf32 pre-conversion of gating_w / output_w
// ---------------------------------------------------------------------------
__global__ void k0_convert(const float* __restrict__ gw, const float* __restrict__ ow) {
    int i = blockIdx.x * 256 + threadIdx.x;   // 4096 total
    g_w1tf[i] = __uint_as_float(f2tf32(gw[i]));
    g_w2tf[i] = __uint_as_float(f2tf32(ow[i]));
}

// ---------------------------------------------------------------------------
// Kernel 1: masked mean of q_data over N  -> g_qavg  (float4 loads)
// 512 threads: 32 row-groups x 16 lanes, each lane one float4 of channels.
// ---------------------------------------------------------------------------
__global__ void __launch_bounds__(512) k1_qavg(const float* __restrict__ q_data,
                                               const float* __restrict__ q_mask) {
    int b = blockIdx.x;
    int t = threadIdx.x;
    int g = t >> 4;          // 0..31
    int l = t & 15;          // float4 index within row
    const float4* qp = (const float4*)(q_data + (size_t)b * NN * QDIM);
    const float* mb = q_mask + (size_t)b * NN;
    float4 acc = make_float4(0.f, 0.f, 0.f, 0.f);
    float ms = 0.f;
    for (int n = g; n < NN; n += 32) {
        float qm = mb[n];
        float4 qv = qp[(size_t)n * 16 + l];
        acc.x += qm * qv.x; acc.y += qm * qv.y;
        acc.z += qm * qv.z; acc.w += qm * qv.w;
        ms += qm;
    }
    __shared__ __align__(16) float sm[32][64];
    __shared__ float smm[32];
    *(float4*)&sm[g][l * 4] = acc;
    if (l == 0) smm[g] = ms;
    __syncthreads();
    if (t < 64) {
        float tot = 0.f, mt = 0.f;
        #pragma unroll
        for (int gg = 0; gg < 32; ++gg) { tot += sm[gg][t]; mt += smm[gg]; }
        g_qavg[b * QDIM + t] = tot / (mt + 1e-10f);
    }
}

// ---------------------------------------------------------------------------
// Kernel 2: per-batch attention -> g_wavg[b][h*8+v]
// main dot-product loop uses packed fma.rn.f32x2 (FFMA2).
// ---------------------------------------------------------------------------
__global__ void __launch_bounds__(256) k2_attn(
    const float* __restrict__ m_data, const float* __restrict__ q_mask,
    const float* __restrict__ query_w, const float* __restrict__ key_w,
    const float* __restrict__ value_w)
{
    int b = blockIdx.x;
    int t = threadIdx.x;

    __shared__ __align__(16) float kw_s[QDIM][KDIM];   // [64][8]
    __shared__ __align__(16) float vw_s[QDIM][VDIM];   // [64][8]
    __shared__ __align__(16) float p_s[QDIM][HH];      // [64][8] : key_w @ q
    __shared__ float qs_s[HH * KDIM];
    __shared__ float qavg_s[QDIM];

    if (t < QDIM) qavg_s[t] = g_qavg[b * QDIM + t];
    for (int i = t; i < QDIM * KDIM; i += 256) {
        kw_s[i >> 3][i & 7] = key_w[i];
        vw_s[i >> 3][i & 7] = value_w[i];
    }
    __syncthreads();
    if (t < 64) {
        float v = 0.f;
        for (int a = 0; a < QDIM; ++a) v += qavg_s[a] * query_w[a * 64 + t];
        qs_s[t] = v * 0.3535533905932738f;   // KD^-0.5
    }
    __syncthreads();
    for (int i = t; i < QDIM * HH; i += 256) {
        int a = i >> 3, h = i & 7;
        float v = 0.f;
        #pragma unroll
        for (int kd = 0; kd < 8; ++kd) v += kw_s[a][kd] * qs_s[h * 8 + kd];
        p_s[a][h] = v;
    }
    __syncthreads();

    float mx[HH], sum[HH], acc[HH][VDIM];
    #pragma unroll
    for (int h = 0; h < HH; ++h) {
        mx[h] = -1e30f; sum[h] = 0.f;
        #pragma unroll
        for (int c = 0; c < VDIM; ++c) acc[h][c] = 0.f;
    }

    const float4* mp4 = (const float4*)(m_data + (size_t)b * NN * QDIM);
    const float* qmp = q_mask + (size_t)b * NN;

    for (int it = 0; it < NN / 256; ++it) {
        int n = t + it * 256;
        float bias = 32768.f * (qmp[n] - 1.f);
        ull lg2[4], v2[4];
        #pragma unroll
        for (int j = 0; j < 4; ++j) { lg2[j] = pack2(bias, bias); v2[j] = pack2(0.f, 0.f); }
        const float4* mp = mp4 + (size_t)n * (QDIM / 4);
        #pragma unroll 4
        for (int a4 = 0; a4 < 16; ++a4) {
            float4 mv = mp[a4];
            float mvals[4] = {mv.x, mv.y, mv.z, mv.w};
            #pragma unroll
            for (int j4 = 0; j4 < 4; ++j4) {
                int a = a4 * 4 + j4;
                ull mmp = pack2(mvals[j4], mvals[j4]);
                const ull* pp = (const ull*)&p_s[a][0];
                const ull* vp = (const ull*)&vw_s[a][0];
                #pragma unroll
                for (int j = 0; j < 4; ++j) {
                    lg2[j] = fma2(mmp, pp[j], lg2[j]);
                    v2[j] = fma2(mmp, vp[j], v2[j]);
                }
            }
        }
        float lg[HH], v[VDIM];
        #pragma unroll
        for (int j = 0; j < 4; ++j) {
            unpack2(lg2[j], lg[2 * j], lg[2 * j + 1]);
            unpack2(v2[j], v[2 * j], v[2 * j + 1]);
        }
        #pragma unroll
        for (int h = 0; h < HH; ++h) {
            float M = fmaxf(mx[h], lg[h]);
            float sc = __expf(mx[h] - M);
            float p = __expf(lg[h] - M);
            sum[h] = sum[h] * sc + p;
            #pragma unroll
            for (int c = 0; c < VDIM; ++c) acc[h][c] = acc[h][c] * sc + p * v[c];
            mx[h] = M;
        }
    }

    #pragma unroll
    for (int off = 16; off; off >>= 1) {
        #pragma unroll
        for (int h = 0; h < HH; ++h) {
            float m2 = __shfl_xor_sync(0xffffffffu, mx[h], off);
            float s2 = __shfl_xor_sync(0xffffffffu, sum[h], off);
            float M = fmaxf(mx[h], m2);
            float e1 = __expf(mx[h] - M);
            float e2 = __expf(m2 - M);
            sum[h] = sum[h] * e1 + s2 * e2;
            #pragma unroll
            for (int c = 0; c < VDIM; ++c) {
                float a2 = __shfl_xor_sync(0xffffffffu, acc[h][c], off);
                acc[h][c] = acc[h][c] * e1 + a2 * e2;
            }
            mx[h] = M;
        }
    }

    __shared__ float red[8][HH][10];
    int w = t >> 5, lane = t & 31;
    if (lane == 0) {
        #pragma unroll
        for (int h = 0; h < HH; ++h) {
            red[w][h][0] = mx[h];
            red[w][h][1] = sum[h];
            #pragma unroll
            for (int c = 0; c < 8; ++c) red[w][h][2 + c] = acc[h][c];
        }
    }
    __syncthreads();
    if (t < HH) {
        int h = t;
        float M = -1e30f, S = 0.f, A[8];
        #pragma unroll
        for (int c = 0; c < 8; ++c) A[c] = 0.f;
        for (int w2 = 0; w2 < 8; ++w2) {
            float m2 = red[w2][h][0], s2 = red[w2][h][1];
            float Mn = fmaxf(M, m2);
            float e1 = __expf(M - Mn), e2 = __expf(m2 - Mn);
            S = S * e1 + s2 * e2;
            #pragma unroll
            for (int c = 0; c < 8; ++c) A[c] = A[c] * e1 + red[w2][h][2 + c] * e2;
            M = Mn;
        }
        float inv = 1.f / S;
        #pragma unroll
        for (int c = 0; c < 8; ++c) g_wavg[b * 64 + h * 8 + c] = A[c] * inv;
    }
}

// ---------------------------------------------------------------------------
// Kernel 3: tf32 mma gate path, 256-token tiles, 8 warps.
// Each warp: m=32 rows (2 m-tiles), n=64 cols (8 n-tiles) -> 1.5 LDS/MMA.
//   A pitch 68 (4 mod 32): A-frag banks 4*gid+tid4 -> conflict-free
//   W pitch 72 (8 mod 32): B-frag banks 8*tid4+8*nt+gid -> conflict-free
// ---------------------------------------------------------------------------
#define TILE_T 256
#define AP 68
#define WP 72
#define K3_SMEM_FLOATS (2 * 64 * WP + TILE_T * AP)   // 26624 floats = 106496 B

__global__ void __launch_bounds__(256, 2) k3_gate(
    const float* __restrict__ q_data,
    const float* __restrict__ gating_b,
    const float* __restrict__ output_b,
    float* __restrict__ out)
{
    extern __shared__ float smem[];
    float* W1 = smem;                       // [64][WP] tf32
    float* W2 = smem + 64 * WP;             // [64][WP] tf32
    float* A  = smem + 2 * 64 * WP;         // [256][AP] row-major
    __shared__ float b1s[64], b2s[64], was[64];

    int t = threadIdx.x;
    size_t tok0 = (size_t)blockIdx.x * TILE_T;
    int b = (int)(tok0 >> 11);

    // pre-converted weights -> smem (pure float4 copies)
    {
        const float4* w1p = (const float4*)g_w1tf;
        const float4* w2p = (const float4*)g_w2tf;
        for (int i = t; i < 1024; i += 256) {
            int k = i >> 4, n = (i & 15) << 2;
            *(float4*)&W1[k * WP + n] = w1p[i];
            *(float4*)&W2[k * WP + n] = w2p[i];
        }
    }
    if (t < 64) {
        b1s[t] = gating_b[t];
        b2s[t] = output_b[t];
        was[t] = g_wavg[b * 64 + t];
    }
    // q tile -> smem (tf32)
    const float4* qp = (const float4*)(q_data + tok0 * QDIM);
    for (int i = t; i < TILE_T * 16; i += 256) {
        float4 v = qp[i];
        int row = i >> 4;
        int k = (i & 15) << 2;
        float* dst = &A[row * AP + k];
        dst[0] = __uint_as_float(f2tf32(v.x));
        dst[1] = __uint_as_float(f2tf32(v.y));
        dst[2] = __uint_as_float(f2tf32(v.z));
        dst[3] = __uint_as_float(f2tf32(v.w));
    }
    __syncthreads();

    int w = t >> 5, lane = t & 31;
    int gid = lane >> 2, tid4 = lane & 3;
    int row0 = w * 32;

    // ---------------- GEMM1: C = A @ W1 ----------------
    float c1[2][8][4];
    #pragma unroll
    for (int mt = 0; mt < 2; ++mt)
        #pragma unroll
        for (int nt = 0; nt < 8; ++nt)
            #pragma unroll
            for (int j = 0; j < 4; ++j) c1[mt][nt][j] = 0.f;

    #pragma unroll
    for (int k0 = 0; k0 < 8; ++k0) {
        int kk = k0 * 8;
        const float* Ar = &A[(row0 + gid) * AP + kk + tid4];
        uint32_t a0[4], a1[4];
        a0[0] = __float_as_uint(Ar[0]);
        a0[1] = __float_as_uint(Ar[8 * AP]);
        a0[2] = __float_as_uint(Ar[4]);
        a0[3] = __float_as_uint(Ar[8 * AP + 4]);
        a1[0] = __float_as_uint(Ar[16 * AP]);
        a1[1] = __float_as_uint(Ar[24 * AP]);
        a1[2] = __float_as_uint(Ar[16 * AP + 4]);
        a1[3] = __float_as_uint(Ar[24 * AP + 4]);
        #pragma unroll
        for (int nt = 0; nt < 8; ++nt) {
            uint32_t bf[2];
            const float* Bp = &W1[(kk + tid4) * WP + nt * 8 + gid];
            bf[0] = __float_as_uint(Bp[0]);
            bf[1] = __float_as_uint(Bp[4 * WP]);
            mma_tf32(c1[0][nt], a0, bf);
            mma_tf32(c1[1][nt], a1, bf);
        }
    }

    // ---------------- gate, write back into A (tf32) ----------------
    __syncthreads();
    #pragma unroll
    for (int mt = 0; mt < 2; ++mt) {
        #pragma unroll
        for (int nt = 0; nt < 8; ++nt) {
            int col = nt * 8 + 2 * tid4;
            float bl0 = b1s[col], bl1 = b1s[col + 1];
            float wl0 = was[col], wl1 = was[col + 1];
            int r0 = row0 + mt * 16 + gid, r1 = r0 + 8;
            float g00 = wl0 / (1.f + __expf(-(c1[mt][nt][0] + bl0)));
            float g01 = wl1 / (1.f + __expf(-(c1[mt][nt][1] + bl1)));
            float g10 = wl0 / (1.f + __expf(-(c1[mt][nt][2] + bl0)));
            float g11 = wl1 / (1.f + __expf(-(c1[mt][nt][3] + bl1)));
            A[r0 * AP + col]     = __uint_as_float(f2tf32(g00));
            A[r0 * AP + col + 1] = __uint_as_float(f2tf32(g01));
            A[r1 * AP + col]     = __uint_as_float(f2tf32(g10));
            A[r1 * AP + col + 1] = __uint_as_float(f2tf32(g11));
        }
    }
    __syncthreads();

    // ---------------- GEMM2: out = G @ W2 + b2 ----------------
    float c2[2][8][4];
    #pragma unroll
    for (int mt = 0; mt < 2; ++mt)
        #pragma unroll
        for (int nt = 0; nt < 8; ++nt)
            #pragma unroll
            for (int j = 0; j < 4; ++j) c2[mt][nt][j] = 0.f;

    #pragma unroll
    for (int k0 = 0; k0 < 8; ++k0) {
        int kk = k0 * 8;
        const float* Ar = &A[(row0 + gid) * AP + kk + tid4];
        uint32_t a0[4], a1[4];
        a0[0] = __float_as_uint(Ar[0]);
        a0[1] = __float_as_uint(Ar[8 * AP]);
        a0[2] = __float_as_uint(Ar[4]);
        a0[3] = __float_as_uint(Ar[8 * AP + 4]);
        a1[0] = __float_as_uint(Ar[16 * AP]);
        a1[1] = __float_as_uint(Ar[24 * AP]);
        a1[2] = __float_as_uint(Ar[16 * AP + 4]);
        a1[3] = __float_as_uint(Ar[24 * AP + 4]);
        #pragma unroll
        for (int nt = 0; nt < 8; ++nt) {
            uint32_t bf[2];
            const float* Bp = &W2[(kk + tid4) * WP + nt * 8 + gid];
            bf[0] = __float_as_uint(Bp[0]);
            bf[1] = __float_as_uint(Bp[4 * WP]);
            mma_tf32(c2[0][nt], a0, bf);
            mma_tf32(c2[1][nt], a1, bf);
        }
    }

    // stage (with bias) then coalesced float4 store
    __syncthreads();
    #pragma unroll
    for (int mt = 0; mt < 2; ++mt) {
        #pragma unroll
        for (int nt = 0; nt < 8; ++nt) {
            int col = nt * 8 + 2 * tid4;
            float bl0 = b2s[col], bl1 = b2s[col + 1];
            int r0 = row0 + mt * 16 + gid, r1 = r0 + 8;
            A[r0 * AP + col]     = c2[mt][nt][0] + bl0;
            A[r0 * AP + col + 1] = c2[mt][nt][1] + bl1;
            A[r1 * AP + col]     = c2[mt][nt][2] + bl0;
            A[r1 * AP + col + 1] = c2[mt][nt][3] + bl1;
        }
    }
    __syncthreads();

    float4* op = (float4*)(out + tok0 * ODIM);
    for (int i = t; i < TILE_T * 16; i += 256) {
        int row = i >> 4;
        int k = (i & 15) << 2;
        op[i] = *(const float4*)&A[row * AP + k];
    }
}

// ---------------------------------------------------------------------------
extern "C" void kernel_launch(void* const* d_in, const int* in_sizes, int n_in,
                              void* d_out, int out_size) {
    (void)in_sizes; (void)n_in; (void)out_size;
    const float* q_data   = (const float*)d_in[0];
    const float* m_data   = (const float*)d_in[1];
    const float* q_mask   = (const float*)d_in[2];
    // d_in[3] = bias (dummy)
    const float* query_w  = (const float*)d_in[4];
    const float* key_w    = (const float*)d_in[5];
    const float* value_w  = (const float*)d_in[6];
    const float* gating_w = (const float*)d_in[7];
    const float* gating_b = (const float*)d_in[8];
    const float* output_w = (const float*)d_in[9];
    const float* output_b = (const float*)d_in[10];
    float* out = (float*)d_out;

    const int k3_smem = K3_SMEM_FLOATS * 4;   // 106496 B
    cudaFuncSetAttribute(k3_gate, cudaFuncAttributeMaxDynamicSharedMemorySize, k3_smem);

    k0_convert<<<16, 256>>>(gating_w, output_w);
    k1_qavg<<<BB, 512>>>(q_data, q_mask);
    k2_attn<<<BB, 256>>>(m_data, q_mask, query_w, key_w, value_w);
    k3_gate<<<(BB * NN) / TILE_T, 256, k3_smem>>>(q_data, gating_b, output_b, out);
}

// round 10
// speedup vs baseline: 1.5819x; 1.5819x over previous
#include <cuda_runtime.h>
#include <cuda_fp16.h>
#include <cstdint>

#define BB 512
#define NN 2048
#define QDIM 64
#define HH 8
#define KDIM 8
#define VDIM 8
#define ODIM 64

// device scratch (no allocations allowed)
__device__ float g_qavg[BB * QDIM];          // [B][64]
__device__ float g_wavg[BB * HH * VDIM];     // [B][64]
__device__ __half g_w1h[QDIM * 64];          // gating_w transposed [n][k] fp16
__device__ __half g_w2h[QDIM * 64];          // output_w transposed [n][k] fp16

// ---------------------------------------------------------------------------
// helpers
// ---------------------------------------------------------------------------
__device__ __forceinline__ void ldsm_x4(uint32_t r[4], uint32_t saddr) {
    asm volatile("ldmatrix.sync.aligned.m8n8.x4.shared.b16 {%0,%1,%2,%3}, [%4];"
                 : "=r"(r[0]), "=r"(r[1]), "=r"(r[2]), "=r"(r[3]) : "r"(saddr));
}

__device__ __forceinline__ void mma_f16(float c[4], const uint32_t a[4],
                                        uint32_t b0, uint32_t b1) {
    asm volatile(
        "mma.sync.aligned.m16n8k16.row.col.f32.f16.f16.f32 "
        "{%0,%1,%2,%3}, {%4,%5,%6,%7}, {%8,%9}, {%0,%1,%2,%3};"
        : "+f"(c[0]), "+f"(c[1]), "+f"(c[2]), "+f"(c[3])
        : "r"(a[0]), "r"(a[1]), "r"(a[2]), "r"(a[3]), "r"(b0), "r"(b1));
}

// ---------------------------------------------------------------------------
// Kernel 0: one-time fp16 pre-conversion + transpose of gating_w / output_w.
// gmem weights are [k][n]; store [n][k] so B operand is col-major for mma.
// ---------------------------------------------------------------------------
__global__ void k0_convert(const float* __restrict__ gw, const float* __restrict__ ow) {
    int i = blockIdx.x * 256 + threadIdx.x;   // 4096 total, i = k*64+n
    int k = i >> 6, n = i & 63;
    g_w1h[n * 64 + k] = __float2half_rn(gw[i]);
    g_w2h[n * 64 + k] = __float2half_rn(ow[i]);
}

// ---------------------------------------------------------------------------
// Kernel 1: masked mean of q_data over N  -> g_qavg  (float4 loads)
// ---------------------------------------------------------------------------
__global__ void __launch_bounds__(512) k1_qavg(const float* __restrict__ q_data,
                                               const float* __restrict__ q_mask) {
    int b = blockIdx.x;
    int t = threadIdx.x;
    int g = t >> 4;          // 0..31
    int l = t & 15;          // float4 index within row
    const float4* qp = (const float4*)(q_data + (size_t)b * NN * QDIM);
    const float* mb = q_mask + (size_t)b * NN;
    float4 acc = make_float4(0.f, 0.f, 0.f, 0.f);
    float ms = 0.f;
    for (int n = g; n < NN; n += 32) {
        float qm = mb[n];
        float4 qv = qp[(size_t)n * 16 + l];
        acc.x += qm * qv.x; acc.y += qm * qv.y;
        acc.z += qm * qv.z; acc.w += qm * qv.w;
        ms += qm;
    }
    __shared__ __align__(16) float sm[32][64];
    __shared__ float smm[32];
    *(float4*)&sm[g][l * 4] = acc;
    if (l == 0) smm[g] = ms;
    __syncthreads();
    if (t < 64) {
        float tot = 0.f, mt = 0.f;
        #pragma unroll
        for (int gg = 0; gg < 32; ++gg) { tot += sm[gg][t]; mt += smm[gg]; }
        g_qavg[b * QDIM + t] = tot / (mt + 1e-10f);
    }
}

// ---------------------------------------------------------------------------
// Kernel 2: per-batch attention -> g_wavg[b][h*8+v]  (R3 known-good version)
// ---------------------------------------------------------------------------
__global__ void __launch_bounds__(256) k2_attn(
    const float* __restrict__ m_data, const float* __restrict__ q_mask,
    const float* __restrict__ query_w, const float* __restrict__ key_w,
    const float* __restrict__ value_w)
{
    int b = blockIdx.x;
    int t = threadIdx.x;

    __shared__ __align__(16) float kw_s[QDIM][KDIM];
    __shared__ __align__(16) float vw_s[QDIM][VDIM];
    __shared__ __align__(16) float p_s[QDIM][HH];
    __shared__ float qs_s[HH * KDIM];
    __shared__ float qavg_s[QDIM];

    if (t < QDIM) qavg_s[t] = g_qavg[b * QDIM + t];
    for (int i = t; i < QDIM * KDIM; i += 256) {
        kw_s[i >> 3][i & 7] = key_w[i];
        vw_s[i >> 3][i & 7] = value_w[i];
    }
    __syncthreads();
    if (t < 64) {
        float v = 0.f;
        for (int a = 0; a < QDIM; ++a) v += qavg_s[a] * query_w[a * 64 + t];
        qs_s[t] = v * 0.3535533905932738f;   // KD^-0.5
    }
    __syncthreads();
    for (int i = t; i < QDIM * HH; i += 256) {
        int a = i >> 3, h = i & 7;
        float v = 0.f;
        #pragma unroll
        for (int kd = 0; kd < 8; ++kd) v += kw_s[a][kd] * qs_s[h * 8 + kd];
        p_s[a][h] = v;
    }
    __syncthreads();

    float mx[HH], sum[HH], acc[HH][VDIM];
    #pragma unroll
    for (int h = 0; h < HH; ++h) {
        mx[h] = -1e30f; sum[h] = 0.f;
        #pragma unroll
        for (int c = 0; c < VDIM; ++c) acc[h][c] = 0.f;
    }

    const float4* mp4 = (const float4*)(m_data + (size_t)b * NN * QDIM);
    const float* qmp = q_mask + (size_t)b * NN;

    for (int it = 0; it < NN / 256; ++it) {
        int n = t + it * 256;
        float bias = 32768.f * (qmp[n] - 1.f);
        float lg[HH];
        float v[VDIM];
        #pragma unroll
        for (int h = 0; h < HH; ++h) lg[h] = bias;
        #pragma unroll
        for (int c = 0; c < VDIM; ++c) v[c] = 0.f;
        const float4* mp = mp4 + (size_t)n * (QDIM / 4);
        #pragma unroll 4
        for (int a4 = 0; a4 < 16; ++a4) {
            float4 mv = mp[a4];
            float mvals[4] = {mv.x, mv.y, mv.z, mv.w};
            #pragma unroll
            for (int j = 0; j < 4; ++j) {
                int a = a4 * 4 + j;
                float mm = mvals[j];
                const float4* pp = (const float4*)&p_s[a][0];
                const float4* vp = (const float4*)&vw_s[a][0];
                float4 p0 = pp[0], p1 = pp[1];
                float4 v0 = vp[0], v1 = vp[1];
                lg[0] += mm * p0.x; lg[1] += mm * p0.y; lg[2] += mm * p0.z; lg[3] += mm * p0.w;
                lg[4] += mm * p1.x; lg[5] += mm * p1.y; lg[6] += mm * p1.z; lg[7] += mm * p1.w;
                v[0] += mm * v0.x; v[1] += mm * v0.y; v[2] += mm * v0.z; v[3] += mm * v0.w;
                v[4] += mm * v1.x; v[5] += mm * v1.y; v[6] += mm * v1.z; v[7] += mm * v1.w;
            }
        }
        #pragma unroll
        for (int h = 0; h < HH; ++h) {
            float M = fmaxf(mx[h], lg[h]);
            float sc = __expf(mx[h] - M);
            float p = __expf(lg[h] - M);
            sum[h] = sum[h] * sc + p;
            #pragma unroll
            for (int c = 0; c < VDIM; ++c) acc[h][c] = acc[h][c] * sc + p * v[c];
            mx[h] = M;
        }
    }

    #pragma unroll
    for (int off = 16; off; off >>= 1) {
        #pragma unroll
        for (int h = 0; h < HH; ++h) {
            float m2 = __shfl_xor_sync(0xffffffffu, mx[h], off);
            float s2 = __shfl_xor_sync(0xffffffffu, sum[h], off);
            float M = fmaxf(mx[h], m2);
            float e1 = __expf(mx[h] - M);
            float e2 = __expf(m2 - M);
            sum[h] = sum[h] * e1 + s2 * e2;
            #pragma unroll
            for (int c = 0; c < VDIM; ++c) {
                float a2 = __shfl_xor_sync(0xffffffffu, acc[h][c], off);
                acc[h][c] = acc[h][c] * e1 + a2 * e2;
            }
            mx[h] = M;
        }
    }

    __shared__ float red[8][HH][10];
    int w = t >> 5, lane = t & 31;
    if (lane == 0) {
        #pragma unroll
        for (int h = 0; h < HH; ++h) {
            red[w][h][0] = mx[h];
            red[w][h][1] = sum[h];
            #pragma unroll
            for (int c = 0; c < 8; ++c) red[w][h][2 + c] = acc[h][c];
        }
    }
    __syncthreads();
    if (t < HH) {
        int h = t;
        float M = -1e30f, S = 0.f, A[8];
        #pragma unroll
        for (int c = 0; c < 8; ++c) A[c] = 0.f;
        for (int w2 = 0; w2 < 8; ++w2) {
            float m2 = red[w2][h][0], s2 = red[w2][h][1];
            float Mn = fmaxf(M, m2);
            float e1 = __expf(M - Mn), e2 = __expf(m2 - Mn);
            S = S * e1 + s2 * e2;
            #pragma unroll
            for (int c = 0; c < 8; ++c) A[c] = A[c] * e1 + red[w2][h][2 + c] * e2;
            M = Mn;
        }
        float inv = 1.f / S;
        #pragma unroll
        for (int c = 0; c < 8; ++c) g_wavg[b * 64 + h * 8 + c] = A[c] * inv;
    }
}

// ---------------------------------------------------------------------------
// Kernel 3: fp16 mma.m16n8k16 gate path with ldmatrix fragments.
// TILE_T=128 tokens/block, 256 threads = 8 warps (4 m-rows x 2 n-cols).
// Warp tile m32 x n32: 32 f32 accums -> no reg cap, ~3 blocks/SM.
// smem pitch = 72 halves (36 u32 == 4 mod 32) -> conflict-free LDSM phases
// and conflict-free half2/float2 epilogue stores.
// ---------------------------------------------------------------------------
#define TILE_T 128
#define WPH 72
#define SM_W1H 0
#define SM_W2H 4608
#define SM_AH  9216
#define K3_SMEM_BYTES ((9216 + TILE_T * WPH) * 2)   // 36864 B

__global__ void __launch_bounds__(256) k3_gate(
    const float* __restrict__ q_data,
    const float* __restrict__ gating_b,
    const float* __restrict__ output_b,
    float* __restrict__ out)
{
    extern __shared__ __align__(16) __half smem_h[];
    __half* W1 = smem_h + SM_W1H;       // [64][WPH]  (n-major, k contiguous)
    __half* W2 = smem_h + SM_W2H;       // [64][WPH]
    __half* A  = smem_h + SM_AH;        // [128][WPH] (row-major tokens x k)
    __shared__ float b1s[64], b2s[64], was[64];

    int t = threadIdx.x;
    size_t tok0 = (size_t)blockIdx.x * TILE_T;
    int b = (int)(tok0 >> 11);

    // weights: g_w*h is [n][k] fp16, copy to pitch-WPH smem (u32 moves)
    {
        const uint32_t* s1 = (const uint32_t*)g_w1h;
        const uint32_t* s2 = (const uint32_t*)g_w2h;
        uint32_t* d1 = (uint32_t*)W1;
        uint32_t* d2 = (uint32_t*)W2;
        #pragma unroll
        for (int j = t; j < 2048; j += 256) {
            int n = j >> 5, kp = j & 31;
            d1[n * (WPH / 2) + kp] = s1[j];
            d2[n * (WPH / 2) + kp] = s2[j];
        }
    }
    if (t < 64) {
        b1s[t] = gating_b[t];
        b2s[t] = output_b[t];
        was[t] = g_wavg[b * 64 + t];
    }
    // q tile -> fp16 smem
    const float4* qp = (const float4*)(q_data + tok0 * QDIM);
    #pragma unroll
    for (int i = t; i < TILE_T * 16; i += 256) {
        float4 v = qp[i];
        int row = i >> 4;
        int k = (i & 15) << 2;
        *(half2*)&A[row * WPH + k]     = __floats2half2_rn(v.x, v.y);
        *(half2*)&A[row * WPH + k + 2] = __floats2half2_rn(v.z, v.w);
    }
    __syncthreads();

    uint32_t sbase = (uint32_t)__cvta_generic_to_shared(smem_h);
    int w = t >> 5, lane = t & 31;
    int gid = lane >> 2, tid4 = lane & 3;
    int wm = w >> 1, wn = w & 1;
    int row0 = wm * 32, n0 = wn * 32;

    // per-thread ldmatrix source offsets (element indices, reused both GEMMs)
    int l7 = lane & 7;
    // A x4 tile: rows {base+l7, base+8+l7} x khalf {0,8}
    int a_r  = l7 + ((lane >> 3) & 1) * 8;      // row within 16-block
    int a_kh = (lane >> 4) * 8;                 // k-half offset
    // B x4 tile: n {octet0, octet1} x khalf {0,8} -> b-frags for 2 n-tiles
    int b_n  = ((lane >> 4) << 3) + l7;         // n within 16-block
    int b_kh = ((lane >> 3) & 1) * 8;

    float c[2][4][4];

    // ================= GEMM1: A @ W1^T (W1 stored [n][k]) =================
    #pragma unroll
    for (int mt = 0; mt < 2; ++mt)
        #pragma unroll
        for (int nt = 0; nt < 4; ++nt)
            #pragma unroll
            for (int j = 0; j < 4; ++j) c[mt][nt][j] = 0.f;

    #pragma unroll
    for (int k0 = 0; k0 < 4; ++k0) {
        int kk = k0 * 16;
        uint32_t am[2][4], bb[2][4];
        #pragma unroll
        for (int mt = 0; mt < 2; ++mt) {
            uint32_t ad = sbase + (uint32_t)(SM_AH +
                (row0 + mt * 16 + a_r) * WPH + kk + a_kh) * 2u;
            ldsm_x4(am[mt], ad);
        }
        #pragma unroll
        for (int bp = 0; bp < 2; ++bp) {
            uint32_t bd = sbase + (uint32_t)(SM_W1H +
                (n0 + bp * 16 + b_n) * WPH + kk + b_kh) * 2u;
            ldsm_x4(bb[bp], bd);
        }
        #pragma unroll
        for (int mt = 0; mt < 2; ++mt) {
            #pragma unroll
            for (int bp = 0; bp < 2; ++bp) {
                mma_f16(c[mt][2 * bp],     am[mt], bb[bp][0], bb[bp][1]);
                mma_f16(c[mt][2 * bp + 1], am[mt], bb[bp][2], bb[bp][3]);
            }
        }
    }

    // ---- gate: sigmoid(+b1) * wavg, write back into A as fp16 ----
    __syncthreads();   // all warps done reading A
    #pragma unroll
    for (int mt = 0; mt < 2; ++mt) {
        #pragma unroll
        for (int nt = 0; nt < 4; ++nt) {
            int col = n0 + nt * 8 + 2 * tid4;
            float bl0 = b1s[col], bl1 = b1s[col + 1];
            float wl0 = was[col], wl1 = was[col + 1];
            int r0 = row0 + mt * 16 + gid, r1 = r0 + 8;
            float g00 = wl0 / (1.f + __expf(-(c[mt][nt][0] + bl0)));
            float g01 = wl1 / (1.f + __expf(-(c[mt][nt][1] + bl1)));
            float g10 = wl0 / (1.f + __expf(-(c[mt][nt][2] + bl0)));
            float g11 = wl1 / (1.f + __expf(-(c[mt][nt][3] + bl1)));
            *(half2*)&A[r0 * WPH + col] = __floats2half2_rn(g00, g01);
            *(half2*)&A[r1 * WPH + col] = __floats2half2_rn(g10, g11);
        }
    }
    __syncthreads();

    // ================= GEMM2: G @ W2^T =================
    #pragma unroll
    for (int mt = 0; mt < 2; ++mt)
        #pragma unroll
        for (int nt = 0; nt < 4; ++nt)
            #pragma unroll
            for (int j = 0; j < 4; ++j) c[mt][nt][j] = 0.f;

    #pragma unroll
    for (int k0 = 0; k0 < 4; ++k0) {
        int kk = k0 * 16;
        uint32_t am[2][4], bb[2][4];
        #pragma unroll
        for (int mt = 0; mt < 2; ++mt) {
            uint32_t ad = sbase + (uint32_t)(SM_AH +
                (row0 + mt * 16 + a_r) * WPH + kk + a_kh) * 2u;
            ldsm_x4(am[mt], ad);
        }
        #pragma unroll
        for (int bp = 0; bp < 2; ++bp) {
            uint32_t bd = sbase + (uint32_t)(SM_W2H +
                (n0 + bp * 16 + b_n) * WPH + kk + b_kh) * 2u;
            ldsm_x4(bb[bp], bd);
        }
        #pragma unroll
        for (int mt = 0; mt < 2; ++mt) {
            #pragma unroll
            for (int bp = 0; bp < 2; ++bp) {
                mma_f16(c[mt][2 * bp],     am[mt], bb[bp][0], bb[bp][1]);
                mma_f16(c[mt][2 * bp + 1], am[mt], bb[bp][2], bb[bp][3]);
            }
        }
    }

    // ---- epilogue: +bias, direct float2 stores (full 32B sectors) ----
    float* op = out + tok0 * ODIM;
    #pragma unroll
    for (int mt = 0; mt < 2; ++mt) {
        #pragma unroll
        for (int nt = 0; nt < 4; ++nt) {
            int col = n0 + nt * 8 + 2 * tid4;
            float bl0 = b2s[col], bl1 = b2s[col + 1];
            int r0 = row0 + mt * 16 + gid, r1 = r0 + 8;
            float2 o0, o1;
            o0.x = c[mt][nt][0] + bl0; o0.y = c[mt][nt][1] + bl1;
            o1.x = c[mt][nt][2] + bl0; o1.y = c[mt][nt][3] + bl1;
            *(float2*)&op[(size_t)r0 * ODIM + col] = o0;
            *(float2*)&op[(size_t)r1 * ODIM + col] = o1;
        }
    }
}

// ---------------------------------------------------------------------------
extern "C" void kernel_launch(void* const* d_in, const int* in_sizes, int n_in,
                              void* d_out, int out_size) {
    (void)in_sizes; (void)n_in; (void)out_size;
    const float* q_data   = (const float*)d_in[0];
    const float* m_data   = (const float*)d_in[1];
    const float* q_mask   = (const float*)d_in[2];
    // d_in[3] = bias (dummy)
    const float* query_w  = (const float*)d_in[4];
    const float* key_w    = (const float*)d_in[5];
    const float* value_w  = (const float*)d_in[6];
    const float* gating_w = (const float*)d_in[7];
    const float* gating_b = (const float*)d_in[8];
    const float* output_w = (const float*)d_in[9];
    const float* output_b = (const float*)d_in[10];
    float* out = (float*)d_out;

    cudaFuncSetAttribute(k3_gate, cudaFuncAttributeMaxDynamicSharedMemorySize,
                         K3_SMEM_BYTES);

    k0_convert<<<16, 256>>>(gating_w, output_w);
    k1_qavg<<<BB, 512>>>(q_data, q_mask);
    k2_attn<<<BB, 256>>>(m_data, q_mask, query_w, key_w, value_w);
    k3_gate<<<(BB * NN) / TILE_T, 256, K3_SMEM_BYTES>>>(q_data, gating_b,
                                                        output_b, out);
}

// round 11
// speedup vs baseline: 2.2317x; 1.4108x over previous
#include <cuda_runtime.h>
#include <cuda_fp16.h>
#include <cstdint>

#define BB 512
#define NN 2048
#define QDIM 64
#define HH 8
#define KDIM 8
#define VDIM 8
#define ODIM 64

// device scratch (no allocations allowed)
__device__ float g_wavg[BB * HH * VDIM];     // [B][64]
__device__ __half g_w1h[QDIM * 64];          // gating_w transposed [n][k] fp16
__device__ __half g_w2h[QDIM * 64];          // output_w transposed [n][k] fp16

// ---------------------------------------------------------------------------
// helpers
// ---------------------------------------------------------------------------
__device__ __forceinline__ void ldsm_x4(uint32_t r[4], uint32_t saddr) {
    asm volatile("ldmatrix.sync.aligned.m8n8.x4.shared.b16 {%0,%1,%2,%3}, [%4];"
                 : "=r"(r[0]), "=r"(r[1]), "=r"(r[2]), "=r"(r[3]) : "r"(saddr));
}

__device__ __forceinline__ void mma_f16(float c[4], const uint32_t a[4],
                                        uint32_t b0, uint32_t b1) {
    asm volatile(
        "mma.sync.aligned.m16n8k16.row.col.f32.f16.f16.f32 "
        "{%0,%1,%2,%3}, {%4,%5,%6,%7}, {%8,%9}, {%0,%1,%2,%3};"
        : "+f"(c[0]), "+f"(c[1]), "+f"(c[2]), "+f"(c[3])
        : "r"(a[0]), "r"(a[1]), "r"(a[2]), "r"(a[3]), "r"(b0), "r"(b1));
}

// ---------------------------------------------------------------------------
// Kernel 0: one-time fp16 pre-conversion + transpose of gating_w / output_w.
// ---------------------------------------------------------------------------
__global__ void k0_convert(const float* __restrict__ gw, const float* __restrict__ ow) {
    int i = blockIdx.x * 256 + threadIdx.x;   // 4096 total, i = k*64+n
    int k = i >> 6, n = i & 63;
    g_w1h[n * 64 + k] = __float2half_rn(gw[i]);
    g_w2h[n * 64 + k] = __float2half_rn(ow[i]);
}

// ---------------------------------------------------------------------------
// Kernel 12 (fused k1+k2): one block per batch, 256 threads (8 warps).
// Stage A: qavg (masked mean) -> q -> P = key_w @ q^T; build fp16 B[16n][64k]
//          (rows 0-7: P^T for logits; rows 8-15: value_w^T for v).
// Main:    stream m in 128-row fp16 tiles (double buffered); per warp one
//          m16k64 x k64n16 MMA chain -> logits & v together; w = mask*exp(l)
//          (no max-subtraction: logits are tiny by construction); accumulate
//          S[h] and acc[h][c] via quad shuffles; hierarchical reduce.
// ---------------------------------------------------------------------------
#define BP 72                                 // B smem pitch (halves)
#define SM_B 0
#define SM_M 2304                             // B: 16*72*2 = 2304 B
#define TILEB (128 * BP * 2)                  // 18432 B per tile buffer
#define K12_SMEM (SM_M + 2 * TILEB)           // 39168 B dynamic

__global__ void __launch_bounds__(256) k12_attn(
    const float* __restrict__ q_data, const float* __restrict__ m_data,
    const float* __restrict__ q_mask, const float* __restrict__ query_w,
    const float* __restrict__ key_w, const float* __restrict__ value_w)
{
    extern __shared__ __align__(16) char smraw[];
    __half* WB = (__half*)(smraw + SM_B);               // [16][BP]
    float* sc = (float*)(smraw + SM_M);                 // stage-A scratch

    __shared__ float qavg_s[64], qs_s[64], kw_s[512], smm[16];
    __shared__ float redA[8][4][8][2];
    __shared__ float redS[8][8];

    int b = blockIdx.x;
    int t = threadIdx.x;

    // ---------------- Stage A1: masked mean of q_data ----------------
    {
        int g = t >> 4, l = t & 15;
        const float4* qp = (const float4*)(q_data + (size_t)b * NN * QDIM);
        const float* mb = q_mask + (size_t)b * NN;
        float4 acc = make_float4(0.f, 0.f, 0.f, 0.f);
        float ms = 0.f;
        #pragma unroll 4
        for (int n = g; n < NN; n += 16) {
            float qm = mb[n];
            float4 qv = qp[(size_t)n * 16 + l];
            acc.x += qm * qv.x; acc.y += qm * qv.y;
            acc.z += qm * qv.z; acc.w += qm * qv.w;
            ms += qm;
        }
        *(float4*)&sc[g * 64 + l * 4] = acc;
        if (l == 0) smm[g] = ms;
        __syncthreads();
        if (t < 64) {
            float tot = 0.f, mt = 0.f;
            #pragma unroll
            for (int gg = 0; gg < 16; ++gg) { tot += sc[gg * 64 + t]; mt += smm[gg]; }
            qavg_s[t] = tot / (mt + 1e-10f);
        }
    }
    // key_w -> smem
    for (int i = t; i < 512; i += 256) kw_s[i] = key_w[i];
    __syncthreads();

    // ---------------- Stage A2: q = (qavg @ query_w)*scale ----------------
    {
        int col = t & 63, seg = t >> 6;       // 4 segments of 16 a's
        float v = 0.f;
        #pragma unroll
        for (int a = seg * 16; a < seg * 16 + 16; ++a)
            v += qavg_s[a] * query_w[a * 64 + col];
        sc[seg * 64 + col] = v;
    }
    __syncthreads();
    if (t < 64)
        qs_s[t] = (sc[t] + sc[64 + t] + sc[128 + t] + sc[192 + t]) * 0.3535533905932738f;
    __syncthreads();

    // ---------------- Stage A3: build B = [P^T ; value_w^T] fp16 ----------------
    for (int i = t; i < 512; i += 256) {
        int a = i >> 3, h = i & 7;
        float p = 0.f;
        #pragma unroll
        for (int kd = 0; kd < 8; ++kd) p += kw_s[a * 8 + kd] * qs_s[h * 8 + kd];
        WB[h * BP + a] = __float2half_rn(p);
    }
    for (int i = t; i < 512; i += 256) {
        int a = i >> 3, c = i & 7;
        WB[(8 + c) * BP + a] = __float2half_rn(value_w[a * 8 + c]);
    }
    __syncthreads();

    // ---------------- fragment geometry ----------------
    uint32_t sbase = (uint32_t)__cvta_generic_to_shared(smraw);
    int w = t >> 5, lane = t & 31;
    int gid = lane >> 2, tid4 = lane & 3;
    int l7 = lane & 7;
    int a_r  = l7 + ((lane >> 3) & 1) * 8;
    int a_kh = (lane >> 4) * 8;
    int b_n  = ((lane >> 4) << 3) + l7;
    int b_kh = ((lane >> 3) & 1) * 8;

    // preload B fragments (constant for whole kernel)
    uint32_t bf[4][4];
    #pragma unroll
    for (int k0 = 0; k0 < 4; ++k0) {
        uint32_t bd = sbase + (uint32_t)(SM_B) + (uint32_t)(b_n * BP + k0 * 16 + b_kh) * 2u;
        ldsm_x4(bf[k0], bd);
    }

    const float4* mp4 = (const float4*)(m_data + (size_t)b * NN * QDIM);
    const float* qmp = q_mask + (size_t)b * NN;

    float acc[8][2], S[8];
    #pragma unroll
    for (int h = 0; h < 8; ++h) { acc[h][0] = 0.f; acc[h][1] = 0.f; S[h] = 0.f; }

    // prologue: load tile 0 into buffer 0
    {
        float4 st[8];
        #pragma unroll
        for (int s = 0; s < 8; ++s) st[s] = mp4[t + 256 * s];
        __half* Mb = (__half*)(smraw + SM_M);
        #pragma unroll
        for (int s = 0; s < 8; ++s) {
            int j = t + 256 * s;
            int row = j >> 4, c4 = j & 15;
            __half2* dst = (__half2*)(Mb + row * BP + c4 * 4);
            dst[0] = __floats2half2_rn(st[s].x, st[s].y);
            dst[1] = __floats2half2_rn(st[s].z, st[s].w);
        }
    }
    __syncthreads();

    // ---------------- main loop: 16 tiles of 128 rows ----------------
    for (int it = 0; it < 16; ++it) {
        int buf = it & 1;
        int rbase = it * 128;

        // prefetch next tile into registers
        float4 st[8];
        if (it < 15) {
            const float4* src = mp4 + (size_t)(rbase + 128) * 16;
            #pragma unroll
            for (int s = 0; s < 8; ++s) st[s] = src[t + 256 * s];
        }

        // ---- compute on current buffer ----
        float c0[4] = {0.f, 0.f, 0.f, 0.f};
        float c1[4] = {0.f, 0.f, 0.f, 0.f};
        uint32_t mb_ad = sbase + (uint32_t)(SM_M + buf * TILEB) +
                         (uint32_t)((w * 16 + a_r) * BP + a_kh) * 2u;
        #pragma unroll
        for (int k0 = 0; k0 < 4; ++k0) {
            uint32_t am[4];
            ldsm_x4(am, mb_ad + k0 * 32u);
            mma_f16(c0, am, bf[k0][0], bf[k0][1]);   // logits (heads 0-7)
            mma_f16(c1, am, bf[k0][2], bf[k0][3]);   // v (channels 0-7)
        }

        float mA = qmp[rbase + w * 16 + gid];
        float mB = qmp[rbase + w * 16 + gid + 8];
        float wA0 = mA * __expf(c0[0]);
        float wA1 = mA * __expf(c0[1]);
        float wB0 = mB * __expf(c0[2]);
        float wB1 = mB * __expf(c0[3]);

        int qb = lane & ~3;
        #pragma unroll
        for (int src = 0; src < 4; ++src) {
            float hA0 = __shfl_sync(0xffffffffu, wA0, qb + src);
            float hA1 = __shfl_sync(0xffffffffu, wA1, qb + src);
            float hB0 = __shfl_sync(0xffffffffu, wB0, qb + src);
            float hB1 = __shfl_sync(0xffffffffu, wB1, qb + src);
            int h0 = 2 * src, h1 = 2 * src + 1;
            acc[h0][0] += hA0 * c1[0]; acc[h0][1] += hA0 * c1[1];
            acc[h1][0] += hA1 * c1[0]; acc[h1][1] += hA1 * c1[1];
            acc[h0][0] += hB0 * c1[2]; acc[h0][1] += hB0 * c1[3];
            acc[h1][0] += hB1 * c1[2]; acc[h1][1] += hB1 * c1[3];
            S[h0] += hA0 + hB0;
            S[h1] += hA1 + hB1;
        }

        // ---- store prefetched tile to other buffer ----
        if (it < 15) {
            __half* Mb = (__half*)(smraw + SM_M + (buf ^ 1) * TILEB);
            #pragma unroll
            for (int s = 0; s < 8; ++s) {
                int j = t + 256 * s;
                int row = j >> 4, c4 = j & 15;
                __half2* dst = (__half2*)(Mb + row * BP + c4 * 4);
                dst[0] = __floats2half2_rn(st[s].x, st[s].y);
                dst[1] = __floats2half2_rn(st[s].z, st[s].w);
            }
        }
        __syncthreads();
    }

    // ---------------- reduction: butterfly over gid, then smem over warps ----
    #pragma unroll
    for (int off = 4; off <= 16; off <<= 1) {
        #pragma unroll
        for (int h = 0; h < 8; ++h) {
            acc[h][0] += __shfl_xor_sync(0xffffffffu, acc[h][0], off);
            acc[h][1] += __shfl_xor_sync(0xffffffffu, acc[h][1], off);
            S[h] += __shfl_xor_sync(0xffffffffu, S[h], off);
        }
    }
    if (lane < 4) {
        #pragma unroll
        for (int h = 0; h < 8; ++h) {
            redA[w][lane][h][0] = acc[h][0];
            redA[w][lane][h][1] = acc[h][1];
        }
        if (lane == 0) {
            #pragma unroll
            for (int h = 0; h < 8; ++h) redS[w][h] = S[h];
        }
    }
    __syncthreads();
    if (t < 64) {
        int h = t >> 3, c = t & 7;
        float a = 0.f, s = 0.f;
        #pragma unroll
        for (int w2 = 0; w2 < 8; ++w2) {
            a += redA[w2][c >> 1][h][c & 1];
            s += redS[w2][h];
        }
        g_wavg[b * 64 + h * 8 + c] = a / s;
    }
}

// ---------------------------------------------------------------------------
// Kernel 3: fp16 mma.m16n8k16 gate path with ldmatrix fragments (R10 version).
// ---------------------------------------------------------------------------
#define TILE_T 128
#define WPH 72
#define SM_W1H 0
#define SM_W2H 4608
#define SM_AH  9216
#define K3_SMEM_BYTES ((9216 + TILE_T * WPH) * 2)   // 36864 B

__global__ void __launch_bounds__(256) k3_gate(
    const float* __restrict__ q_data,
    const float* __restrict__ gating_b,
    const float* __restrict__ output_b,
    float* __restrict__ out)
{
    extern __shared__ __align__(16) __half smem_h[];
    __half* W1 = smem_h + SM_W1H;
    __half* W2 = smem_h + SM_W2H;
    __half* A  = smem_h + SM_AH;
    __shared__ float b1s[64], b2s[64], was[64];

    int t = threadIdx.x;
    size_t tok0 = (size_t)blockIdx.x * TILE_T;
    int b = (int)(tok0 >> 11);

    {
        const uint32_t* s1 = (const uint32_t*)g_w1h;
        const uint32_t* s2 = (const uint32_t*)g_w2h;
        uint32_t* d1 = (uint32_t*)W1;
        uint32_t* d2 = (uint32_t*)W2;
        #pragma unroll
        for (int j = t; j < 2048; j += 256) {
            int n = j >> 5, kp = j & 31;
            d1[n * (WPH / 2) + kp] = s1[j];
            d2[n * (WPH / 2) + kp] = s2[j];
        }
    }
    if (t < 64) {
        b1s[t] = gating_b[t];
        b2s[t] = output_b[t];
        was[t] = g_wavg[b * 64 + t];
    }
    const float4* qp = (const float4*)(q_data + tok0 * QDIM);
    #pragma unroll
    for (int i = t; i < TILE_T * 16; i += 256) {
        float4 v = qp[i];
        int row = i >> 4;
        int k = (i & 15) << 2;
        *(half2*)&A[row * WPH + k]     = __floats2half2_rn(v.x, v.y);
        *(half2*)&A[row * WPH + k + 2] = __floats2half2_rn(v.z, v.w);
    }
    __syncthreads();

    uint32_t sbase = (uint32_t)__cvta_generic_to_shared(smem_h);
    int w = t >> 5, lane = t & 31;
    int gid = lane >> 2, tid4 = lane & 3;
    int wm = w >> 1, wn = w & 1;
    int row0 = wm * 32, n0 = wn * 32;

    int l7 = lane & 7;
    int a_r  = l7 + ((lane >> 3) & 1) * 8;
    int a_kh = (lane >> 4) * 8;
    int b_n  = ((lane >> 4) << 3) + l7;
    int b_kh = ((lane >> 3) & 1) * 8;

    float c[2][4][4];

    #pragma unroll
    for (int mt = 0; mt < 2; ++mt)
        #pragma unroll
        for (int nt = 0; nt < 4; ++nt)
            #pragma unroll
            for (int j = 0; j < 4; ++j) c[mt][nt][j] = 0.f;

    #pragma unroll
    for (int k0 = 0; k0 < 4; ++k0) {
        int kk = k0 * 16;
        uint32_t am[2][4], bb[2][4];
        #pragma unroll
        for (int mt = 0; mt < 2; ++mt) {
            uint32_t ad = sbase + (uint32_t)(SM_AH +
                (row0 + mt * 16 + a_r) * WPH + kk + a_kh) * 2u;
            ldsm_x4(am[mt], ad);
        }
        #pragma unroll
        for (int bp = 0; bp < 2; ++bp) {
            uint32_t bd = sbase + (uint32_t)(SM_W1H +
                (n0 + bp * 16 + b_n) * WPH + kk + b_kh) * 2u;
            ldsm_x4(bb[bp], bd);
        }
        #pragma unroll
        for (int mt = 0; mt < 2; ++mt) {
            #pragma unroll
            for (int bp = 0; bp < 2; ++bp) {
                mma_f16(c[mt][2 * bp],     am[mt], bb[bp][0], bb[bp][1]);
                mma_f16(c[mt][2 * bp + 1], am[mt], bb[bp][2], bb[bp][3]);
            }
        }
    }

    __syncthreads();
    #pragma unroll
    for (int mt = 0; mt < 2; ++mt) {
        #pragma unroll
        for (int nt = 0; nt < 4; ++nt) {
            int col = n0 + nt * 8 + 2 * tid4;
            float bl0 = b1s[col], bl1 = b1s[col + 1];
            float wl0 = was[col], wl1 = was[col + 1];
            int r0 = row0 + mt * 16 + gid, r1 = r0 + 8;
            float g00 = wl0 / (1.f + __expf(-(c[mt][nt][0] + bl0)));
            float g01 = wl1 / (1.f + __expf(-(c[mt][nt][1] + bl1)));
            float g10 = wl0 / (1.f + __expf(-(c[mt][nt][2] + bl0)));
            float g11 = wl1 / (1.f + __expf(-(c[mt][nt][3] + bl1)));
            *(half2*)&A[r0 * WPH + col] = __floats2half2_rn(g00, g01);
            *(half2*)&A[r1 * WPH + col] = __floats2half2_rn(g10, g11);
        }
    }
    __syncthreads();

    #pragma unroll
    for (int mt = 0; mt < 2; ++mt)
        #pragma unroll
        for (int nt = 0; nt < 4; ++nt)
            #pragma unroll
            for (int j = 0; j < 4; ++j) c[mt][nt][j] = 0.f;

    #pragma unroll
    for (int k0 = 0; k0 < 4; ++k0) {
        int kk = k0 * 16;
        uint32_t am[2][4], bb[2][4];
        #pragma unroll
        for (int mt = 0; mt < 2; ++mt) {
            uint32_t ad = sbase + (uint32_t)(SM_AH +
                (row0 + mt * 16 + a_r) * WPH + kk + a_kh) * 2u;
            ldsm_x4(am[mt], ad);
        }
        #pragma unroll
        for (int bp = 0; bp < 2; ++bp) {
            uint32_t bd = sbase + (uint32_t)(SM_W2H +
                (n0 + bp * 16 + b_n) * WPH + kk + b_kh) * 2u;
            ldsm_x4(bb[bp], bd);
        }
        #pragma unroll
        for (int mt = 0; mt < 2; ++mt) {
            #pragma unroll
            for (int bp = 0; bp < 2; ++bp) {
                mma_f16(c[mt][2 * bp],     am[mt], bb[bp][0], bb[bp][1]);
                mma_f16(c[mt][2 * bp + 1], am[mt], bb[bp][2], bb[bp][3]);
            }
        }
    }

    float* op = out + tok0 * ODIM;
    #pragma unroll
    for (int mt = 0; mt < 2; ++mt) {
        #pragma unroll
        for (int nt = 0; nt < 4; ++nt) {
            int col = n0 + nt * 8 + 2 * tid4;
            float bl0 = b2s[col], bl1 = b2s[col + 1];
            int r0 = row0 + mt * 16 + gid, r1 = r0 + 8;
            float2 o0, o1;
            o0.x = c[mt][nt][0] + bl0; o0.y = c[mt][nt][1] + bl1;
            o1.x = c[mt][nt][2] + bl0; o1.y = c[mt][nt][3] + bl1;
            *(float2*)&op[(size_t)r0 * ODIM + col] = o0;
            *(float2*)&op[(size_t)r1 * ODIM + col] = o1;
        }
    }
}

// ---------------------------------------------------------------------------
extern "C" void kernel_launch(void* const* d_in, const int* in_sizes, int n_in,
                              void* d_out, int out_size) {
    (void)in_sizes; (void)n_in; (void)out_size;
    const float* q_data   = (const float*)d_in[0];
    const float* m_data   = (const float*)d_in[1];
    const float* q_mask   = (const float*)d_in[2];
    // d_in[3] = bias (dummy)
    const float* query_w  = (const float*)d_in[4];
    const float* key_w    = (const float*)d_in[5];
    const float* value_w  = (const float*)d_in[6];
    const float* gating_w = (const float*)d_in[7];
    const float* gating_b = (const float*)d_in[8];
    const float* output_w = (const float*)d_in[9];
    const float* output_b = (const float*)d_in[10];
    float* out = (float*)d_out;

    cudaFuncSetAttribute(k12_attn, cudaFuncAttributeMaxDynamicSharedMemorySize,
                         K12_SMEM);
    cudaFuncSetAttribute(k3_gate, cudaFuncAttributeMaxDynamicSharedMemorySize,
                         K3_SMEM_BYTES);

    k0_convert<<<16, 256>>>(gating_w, output_w);
    k12_attn<<<BB, 256, K12_SMEM>>>(q_data, m_data, q_mask, query_w, key_w,
                                    value_w);
    k3_gate<<<(BB * NN) / TILE_T, 256, K3_SMEM_BYTES>>>(q_data, gating_b,
                                                        output_b, out);
}